// round 11
// baseline (speedup 1.0000x reference)
#include <cuda_runtime.h>

// ---------------------------------------------------------------------------
// EASeq2SeqLSTM persistent-kernel fp32, v2.
// B=256, L=365, F=32, S=27, H=256, HOR=24, NT=1.
// 128 CTAs x 256 threads, 1 CTA/SM, software grid barrier.
// CTA tile: 64 batches x 8 units (x4 gates); thread = 1 unit x 4 gates x
// 2 batches -> 8 register accumulators, cell state in registers throughout.
// v2: float4 weight LDS (k-unroll 4), single-pass K=512 staging,
//     x-prefetch overlapped with the grid barrier.
// ---------------------------------------------------------------------------

namespace {
constexpr int B_   = 256;
constexpr int L_   = 365;
constexpr int F_   = 32;
constexpr int S_   = 27;
constexpr int H_   = 256;
constexpr int HOR_ = 24;
constexpr int HB   = H_ * B_;      // 65536
constexpr int NCTA = 128;
constexpr int NTHR = 256;

// shared memory layout (floats), per phase:
//  EA : W at 0 (4*8*288 = 9216),  X at  9216 (288*64 = 18432)  -> 27648
//  ENC: W at 0 (32*512  = 16384), X at 16384 (512*64 = 32768)  -> 49152
//  DEC: W0 at 0 (32*260 = 8320), W1 at 8320 (32*512 = 16384),
//       X at 24704 (512*64 = 32768)                            -> 57472
constexpr int SW_EA   = 9216;
constexpr int SW_ENC  = 16384;
constexpr int SW_DEC  = 24704;
constexpr int SMEM_FLOATS = SW_DEC + 512 * 64;   // 57472
constexpr int SMEM_BYTES  = SMEM_FLOATS * (int)sizeof(float);  // 229888
}

// ------------------------- global scratch ----------------------------------
__device__ float g_xT[L_ * F_ * B_];            // [t][f][b]
__device__ float g_seqT[(size_t)L_ * H_ * B_];  // [t][u][b]
__device__ float g_hEA[2 * HB];                 // ping-pong [u][b]
__device__ float g_hENC[2 * HB];
__device__ float g_hA[2 * HB];
__device__ float g_hB[2 * HB];
__device__ float g_din[B_];
__device__ unsigned g_cnt;
__device__ volatile unsigned g_gen;

// ------------------------- grid barrier ------------------------------------
__device__ __forceinline__ void grid_sync() {
    __threadfence();
    __syncthreads();
    if (threadIdx.x == 0) {
        unsigned gen = g_gen;
        if (atomicAdd(&g_cnt, 1u) == NCTA - 1u) {
            g_cnt = 0u;
            __threadfence();
            g_gen = gen + 1u;
        } else {
            while (g_gen == gen) { }
        }
        __threadfence();
    }
    __syncthreads();
}

// ------------------------- math helpers ------------------------------------
__device__ __forceinline__ float sigf(float v) {
    return __fdividef(1.f, 1.f + __expf(-v));
}
__device__ __forceinline__ float tanh_(float v) {
    float t = __expf(2.f * v);
    return __fdividef(t - 1.f, t + 1.f);
}

// ------------------------- staging: gmem[r*B+b0..] -> smem[r*64..] ---------
__device__ __forceinline__ void stage_rows_cg(float* dst, const float* src,
                                              int nrows, int b0) {
    for (int i = threadIdx.x; i < nrows * 16; i += NTHR) {
        int r = i >> 4, b = (i & 15) << 2;
        *reinterpret_cast<float4*>(dst + r * 64 + b) =
            __ldcg(reinterpret_cast<const float4*>(src + r * B_ + b0 + b));
    }
}

// ------------------------- inner GEMV --------------------------------------
// a[8] = 4 gates x 2 batches. w0 = gate-0 row (float4-aligned), gate rows
// gstride floats apart (gstride % 4 == 0). xs = [k][64] staging, tl = 2*lane.
// K % 4 == 0.
__device__ __forceinline__ void accum8v(float* a, const float* __restrict__ w0,
                                        int gstride, const float* __restrict__ xs,
                                        int K, int tl) {
    const float4* g0 = reinterpret_cast<const float4*>(w0);
    const float4* g1 = reinterpret_cast<const float4*>(w0 + gstride);
    const float4* g2 = reinterpret_cast<const float4*>(w0 + 2 * gstride);
    const float4* g3 = reinterpret_cast<const float4*>(w0 + 3 * gstride);
    const int K4 = K >> 2;
#pragma unroll 2
    for (int k4 = 0; k4 < K4; ++k4) {
        float4 w0v = g0[k4], w1v = g1[k4], w2v = g2[k4], w3v = g3[k4];
        const float* xb = xs + k4 * 256 + tl;
        float2 x0 = *reinterpret_cast<const float2*>(xb);
        float2 x1 = *reinterpret_cast<const float2*>(xb + 64);
        float2 x2 = *reinterpret_cast<const float2*>(xb + 128);
        float2 x3 = *reinterpret_cast<const float2*>(xb + 192);
        a[0] += w0v.x * x0.x; a[1] += w0v.x * x0.y;
        a[2] += w1v.x * x0.x; a[3] += w1v.x * x0.y;
        a[4] += w2v.x * x0.x; a[5] += w2v.x * x0.y;
        a[6] += w3v.x * x0.x; a[7] += w3v.x * x0.y;
        a[0] += w0v.y * x1.x; a[1] += w0v.y * x1.y;
        a[2] += w1v.y * x1.x; a[3] += w1v.y * x1.y;
        a[4] += w2v.y * x1.x; a[5] += w2v.y * x1.y;
        a[6] += w3v.y * x1.x; a[7] += w3v.y * x1.y;
        a[0] += w0v.z * x2.x; a[1] += w0v.z * x2.y;
        a[2] += w1v.z * x2.x; a[3] += w1v.z * x2.y;
        a[4] += w2v.z * x2.x; a[5] += w2v.z * x2.y;
        a[6] += w3v.z * x2.x; a[7] += w3v.z * x2.y;
        a[0] += w0v.w * x3.x; a[1] += w0v.w * x3.y;
        a[2] += w1v.w * x3.x; a[3] += w1v.w * x3.y;
        a[4] += w2v.w * x3.x; a[5] += w2v.w * x3.y;
        a[6] += w3v.w * x3.x; a[7] += w3v.w * x3.y;
    }
}

// ---------------------------------------------------------------------------
__global__ void __launch_bounds__(NTHR, 1)
ea_seq2seq_kernel(const float* __restrict__ x,    const float* __restrict__ s,
                  const float* __restrict__ Wf,   const float* __restrict__ bf,
                  const float* __restrict__ Wo,   const float* __restrict__ bo,
                  const float* __restrict__ Wi,   const float* __restrict__ bi,
                  const float* __restrict__ Wg,   const float* __restrict__ bg,
                  const float* __restrict__ Wsi,  const float* __restrict__ bsi,
                  const float* __restrict__ Wsg,  const float* __restrict__ bsg,
                  const float* __restrict__ eWih, const float* __restrict__ eWhh,
                  const float* __restrict__ ebih, const float* __restrict__ ebhh,
                  const float* __restrict__ dWih0, const float* __restrict__ dWhh0,
                  const float* __restrict__ dbih0, const float* __restrict__ dbhh0,
                  const float* __restrict__ dWih1, const float* __restrict__ dWhh1,
                  const float* __restrict__ dbih1, const float* __restrict__ dbhh1,
                  const float* __restrict__ fcW,  const float* __restrict__ fcb,
                  float* __restrict__ out)
{
    extern __shared__ float smem[];

    const int tid  = threadIdx.x;
    const int bt   = blockIdx.x & 3;
    const int ut   = blockIdx.x >> 2;
    const int b0   = bt * 64;
    const int u0   = ut * 8;
    const int ul   = tid >> 5;
    const int lane = tid & 31;
    const int tl   = lane * 2;
    const int ug   = u0 + ul;
    const int gb   = b0 + tl;

    // ---------------- phase 0: transpose x (float4 over f), zero din -------
    {
        int gt = blockIdx.x * NTHR + tid;
        for (int i = gt; i < L_ * 8 * B_; i += NCTA * NTHR) {
            int t = i / (8 * B_);
            int r = i - t * (8 * B_);
            int f4 = r >> 8;
            int b  = r & 255;
            float4 v = *reinterpret_cast<const float4*>(
                x + (size_t)b * (L_ * F_) + t * F_ + f4 * 4);
            float* dst = g_xT + t * F_ * B_ + (f4 * 4) * B_ + b;
            dst[0]      = v.x;
            dst[B_]     = v.y;
            dst[2 * B_] = v.z;
            dst[3 * B_] = v.w;
        }
        if (blockIdx.x == 0) g_din[tid] = 0.f;
    }

    // static contributions si/sg (+ biases)
    float si0, si1, sg0, sg1;
    {
        si0 = si1 = bsi[ug];
        sg0 = sg1 = bsg[ug];
#pragma unroll
        for (int j = 0; j < S_; ++j) {
            float wiv = Wsi[ug * S_ + j];
            float wgv = Wsg[ug * S_ + j];
            float sv0 = s[gb * S_ + j];
            float sv1 = s[(gb + 1) * S_ + j];
            si0 += wiv * sv0; si1 += wiv * sv1;
            sg0 += wgv * sv0; sg1 += wgv * sv1;
        }
    }

    // EA weights -> smem, gate order f,o,i,g ; row length 288
    {
        float* sW = smem;
        const float* Ws[4] = {Wf, Wo, Wi, Wg};
        for (int i = tid; i < 4 * 8 * 288; i += NTHR) {
            int g = i / (8 * 288);
            int r = i - g * (8 * 288);
            int u = r / 288;
            int k = r - u * 288;
            sW[i] = Ws[g][(u0 + u) * 288 + k];
        }
    }
    const float bF = bf[ug], bO = bo[ug], bI = bi[ug], bG = bg[ug];

    grid_sync();   // x transpose + din visible everywhere

    // ---------------- phase 1: EA-LSTM over L steps ------------------------
    float c0 = 0.f, c1 = 0.f;
    {
        float* sW = smem;
        float* sX = smem + SW_EA;
        // pre-stage step 0: x_0 + zero h
        stage_rows_cg(sX, g_xT, F_, b0);
        for (int i = tid; i < H_ * 64; i += NTHR) sX[F_ * 64 + i] = 0.f;
        __syncthreads();

        int p = 0;
        for (int t = 0; t < L_; ++t) {
            float a[8] = {bF, bF, bO, bO, bI + si0, bI + si1, bG + sg0, bG + sg1};
            accum8v(a, sW + ul * 288, 8 * 288, sX, 288, tl);

            float f0 = sigf(a[0]), f1 = sigf(a[1]);
            float o0 = sigf(a[2]), o1 = sigf(a[3]);
            float i0 = sigf(a[4]), i1 = sigf(a[5]);
            float q0 = tanh_(a[6]), q1 = tanh_(a[7]);
            c0 = f0 * c0 + i0 * q0;
            c1 = f1 * c1 + i1 * q1;
            float2 hv = make_float2(o0 * tanh_(c0), o1 * tanh_(c1));

            *reinterpret_cast<float2*>(g_hEA + (1 - p) * HB + ug * B_ + gb) = hv;
            *reinterpret_cast<float2*>(g_seqT + (size_t)t * HB + ug * B_ + gb) = hv;
            if (t == L_ - 1)
                *reinterpret_cast<float2*>(g_hENC + ug * B_ + gb) = hv;

            __syncthreads();                       // all done reading sX
            if (t + 1 < L_)                        // prefetch x_{t+1} (no dep on barrier)
                stage_rows_cg(sX, g_xT + (t + 1) * F_ * B_, F_, b0);
            grid_sync();                           // publish h_t
            if (t + 1 < L_) {
                stage_rows_cg(sX + F_ * 64, g_hEA + (1 - p) * HB, H_, b0);
                __syncthreads();
            }
            p ^= 1;
        }
    }

    // ---------------- phase 2: encoder LSTM (gate order i,f,g,o) -----------
    {
        float* sW = smem;
        float* sX = smem + SW_ENC;
        for (int i = tid; i < 4 * 8 * 512; i += NTHR) {
            int g = i / (8 * 512);
            int r = i - g * (8 * 512);
            int u = r >> 9;
            int k = r & 511;
            int go = g * H_ + u0 + u;
            sW[i] = (k < 256) ? eWih[go * H_ + k] : eWhh[go * H_ + (k - 256)];
        }
        const float ebI = ebih[0 * H_ + ug] + ebhh[0 * H_ + ug];
        const float ebF = ebih[1 * H_ + ug] + ebhh[1 * H_ + ug];
        const float ebG = ebih[2 * H_ + ug] + ebhh[2 * H_ + ug];
        const float ebO = ebih[3 * H_ + ug] + ebhh[3 * H_ + ug];
        // pre-stage step 0: xt = seq[0], h = hENC[0]  (both published)
        stage_rows_cg(sX, g_seqT, H_, b0);
        stage_rows_cg(sX + 256 * 64, g_hENC, H_, b0);
        __syncthreads();

        int p = 0;   // encoder c inherits EA final c (registers)
        for (int t = 0; t < L_; ++t) {
            float a[8] = {ebI, ebI, ebF, ebF, ebG, ebG, ebO, ebO};
            accum8v(a, sW + ul * 512, 8 * 512, sX, 512, tl);

            float ii0 = sigf(a[0]), ii1 = sigf(a[1]);
            float ff0 = sigf(a[2]), ff1 = sigf(a[3]);
            float qg0 = tanh_(a[4]), qg1 = tanh_(a[5]);
            float oo0 = sigf(a[6]), oo1 = sigf(a[7]);
            c0 = ff0 * c0 + ii0 * qg0;
            c1 = ff1 * c1 + ii1 * qg1;
            float2 hv = make_float2(oo0 * tanh_(c0), oo1 * tanh_(c1));

            *reinterpret_cast<float2*>(g_hENC + (1 - p) * HB + ug * B_ + gb) = hv;
            if (t == L_ - 1) {
                *reinterpret_cast<float2*>(g_hA + ug * B_ + gb) = hv;
                *reinterpret_cast<float2*>(g_hB + ug * B_ + gb) = hv;
            }

            __syncthreads();
            if (t + 1 < L_)
                stage_rows_cg(sX, g_seqT + (size_t)(t + 1) * HB, H_, b0);
            grid_sync();
            if (t + 1 < L_) {
                stage_rows_cg(sX + 256 * 64, g_hENC + (1 - p) * HB, H_, b0);
                __syncthreads();
            }
            p ^= 1;
        }
    }

    // ---------------- phase 3: decoder (2 layers, 24 steps) ----------------
    {
        float* sW0 = smem;                 // 32 rows x 260: [Whh0 | Wih0 | 0,0,0]
        float* sW1 = smem + 8320;          // 32 rows x 512: [Wih1 | Whh1]
        float* sX  = smem + SW_DEC;
        for (int i = tid; i < 32 * 260; i += NTHR) {
            int row = i / 260;
            int k   = i - row * 260;
            int g = row >> 3, u = row & 7;
            int go = g * H_ + u0 + u;
            float v = 0.f;
            if (k < 256)       v = dWhh0[go * H_ + k];
            else if (k == 256) v = dWih0[go];
            sW0[i] = v;
        }
        for (int i = tid; i < 32 * 512; i += NTHR) {
            int row = i >> 9;
            int k   = i & 511;
            int g = row >> 3, u = row & 7;
            int go = g * H_ + u0 + u;
            sW1[i] = (k < 256) ? dWih1[go * H_ + k] : dWhh1[go * H_ + (k - 256)];
        }
        const float d0I = dbih0[0*H_+ug] + dbhh0[0*H_+ug];
        const float d0F = dbih0[1*H_+ug] + dbhh0[1*H_+ug];
        const float d0G = dbih0[2*H_+ug] + dbhh0[2*H_+ug];
        const float d0O = dbih0[3*H_+ug] + dbhh0[3*H_+ug];
        const float d1I = dbih1[0*H_+ug] + dbhh1[0*H_+ug];
        const float d1F = dbih1[1*H_+ug] + dbhh1[1*H_+ug];
        const float d1G = dbih1[2*H_+ug] + dbhh1[2*H_+ug];
        const float d1O = dbih1[3*H_+ug] + dbhh1[3*H_+ug];
        const float fcb0 = fcb[0];
        float cA0 = c0, cA1 = c1, cB0 = c0, cB1 = c1;
        __syncthreads();

        int p = 0;
        for (int st = 0; st < HOR_; ++st) {
            // ---- layer 0: x = [hA(256) | din(1) | pad(3)], K=260 ----
            stage_rows_cg(sX, g_hA + p * HB, H_, b0);
            if (tid < 64)                 sX[256 * 64 + tid] = __ldcg(&g_din[b0 + tid]);
            else if (tid < 256 && tid - 64 < 192) sX[257 * 64 + (tid - 64)] = 0.f;
            __syncthreads();
            {
                float a[8] = {d0I, d0I, d0F, d0F, d0G, d0G, d0O, d0O};
                accum8v(a, sW0 + ul * 260, 8 * 260, sX, 260, tl);
                float ii0 = sigf(a[0]), ii1 = sigf(a[1]);
                float ff0 = sigf(a[2]), ff1 = sigf(a[3]);
                float qg0 = tanh_(a[4]), qg1 = tanh_(a[5]);
                float oo0 = sigf(a[6]), oo1 = sigf(a[7]);
                cA0 = ff0 * cA0 + ii0 * qg0;
                cA1 = ff1 * cA1 + ii1 * qg1;
                float2 hv = make_float2(oo0 * tanh_(cA0), oo1 * tanh_(cA1));
                *reinterpret_cast<float2*>(g_hA + (1 - p) * HB + ug * B_ + gb) = hv;
            }
            grid_sync();

            // ---- layer 1: x = [hA_new(256) | hB(256)], K=512 ----
            stage_rows_cg(sX, g_hA + (1 - p) * HB, H_, b0);
            stage_rows_cg(sX + 256 * 64, g_hB + p * HB, H_, b0);
            __syncthreads();
            {
                float a[8] = {d1I, d1I, d1F, d1F, d1G, d1G, d1O, d1O};
                accum8v(a, sW1 + ul * 512, 8 * 512, sX, 512, tl);
                float ii0 = sigf(a[0]), ii1 = sigf(a[1]);
                float ff0 = sigf(a[2]), ff1 = sigf(a[3]);
                float qg0 = tanh_(a[4]), qg1 = tanh_(a[5]);
                float oo0 = sigf(a[6]), oo1 = sigf(a[7]);
                cB0 = ff0 * cB0 + ii0 * qg0;
                cB1 = ff1 * cB1 + ii1 * qg1;
                float2 hv = make_float2(oo0 * tanh_(cB0), oo1 * tanh_(cB1));
                *reinterpret_cast<float2*>(g_hB + (1 - p) * HB + ug * B_ + gb) = hv;
            }
            grid_sync();

            // ---- output head: pred = hB @ fcW + fcb ----
            if (ut == 0) {
                int bloc = tid >> 2, q = tid & 3;
                int gb2 = b0 + bloc;
                const float* hb = g_hB + (1 - p) * HB;
                float v = 0.f;
#pragma unroll 4
                for (int k = q * 64; k < q * 64 + 64; ++k)
                    v += __ldcg(&hb[k * B_ + gb2]) * fcW[k];
                v += __shfl_xor_sync(0xffffffffu, v, 1);
                v += __shfl_xor_sync(0xffffffffu, v, 2);
                if (q == 0) {
                    float pr = v + fcb0;
                    out[gb2 * HOR_ + st] = pr;
                    g_din[gb2] = pr;
                }
            }
            grid_sync();
            p ^= 1;
        }
    }
}

// ---------------------------------------------------------------------------
extern "C" void kernel_launch(void* const* d_in, const int* in_sizes, int n_in,
                              void* d_out, int out_size) {
    (void)in_sizes; (void)n_in; (void)out_size;
    const float* x     = (const float*)d_in[0];
    const float* s     = (const float*)d_in[1];
    const float* Wf    = (const float*)d_in[2];
    const float* bf    = (const float*)d_in[3];
    const float* Wo    = (const float*)d_in[4];
    const float* bo    = (const float*)d_in[5];
    const float* Wi    = (const float*)d_in[6];
    const float* bi    = (const float*)d_in[7];
    const float* Wg    = (const float*)d_in[8];
    const float* bg    = (const float*)d_in[9];
    const float* Wsi   = (const float*)d_in[10];
    const float* bsi   = (const float*)d_in[11];
    const float* Wsg   = (const float*)d_in[12];
    const float* bsg   = (const float*)d_in[13];
    const float* eWih  = (const float*)d_in[14];
    const float* eWhh  = (const float*)d_in[15];
    const float* ebih  = (const float*)d_in[16];
    const float* ebhh  = (const float*)d_in[17];
    const float* dWih0 = (const float*)d_in[18];
    const float* dWhh0 = (const float*)d_in[19];
    const float* dbih0 = (const float*)d_in[20];
    const float* dbhh0 = (const float*)d_in[21];
    const float* dWih1 = (const float*)d_in[22];
    const float* dWhh1 = (const float*)d_in[23];
    const float* dbih1 = (const float*)d_in[24];
    const float* dbhh1 = (const float*)d_in[25];
    const float* fcW   = (const float*)d_in[26];
    const float* fcb   = (const float*)d_in[27];

    cudaFuncSetAttribute(ea_seq2seq_kernel,
                         cudaFuncAttributeMaxDynamicSharedMemorySize, SMEM_BYTES);
    ea_seq2seq_kernel<<<NCTA, NTHR, SMEM_BYTES>>>(
        x, s, Wf, bf, Wo, bo, Wi, bi, Wg, bg, Wsi, bsi, Wsg, bsg,
        eWih, eWhh, ebih, ebhh,
        dWih0, dWhh0, dbih0, dbhh0, dWih1, dWhh1, dbih1, dbhh1,
        fcW, fcb, (float*)d_out);
}

// round 12
// speedup vs baseline: 1.1166x; 1.1166x over previous
#include <cuda_runtime.h>

// ---------------------------------------------------------------------------
// EASeq2SeqLSTM persistent-kernel fp32, v3.
// B=256, L=365, F=32, S=27, H=256, HOR=24, NT=1.
// 128 CTAs x 256 threads, 1 CTA/SM.
// v3: parallel flag-array grid barrier (no contended atomics),
//     cp.async (.cg) staging overlapped with x-side partial accumulation,
//     EA recurrent h read directly from seqT (no separate ping-pong).
// ---------------------------------------------------------------------------

namespace {
constexpr int B_   = 256;
constexpr int L_   = 365;
constexpr int F_   = 32;
constexpr int S_   = 27;
constexpr int H_   = 256;
constexpr int HOR_ = 24;
constexpr int HB   = H_ * B_;      // 65536
constexpr int NCTA = 128;
constexpr int NTHR = 256;

// smem layout (floats):
//  EA : W 0..9216, X 9216..(9216+288*64)
//  ENC: W 0..16384, X 16384..(16384+512*64)
//  DEC: W0 0..8320, W1 8320..24704, X 24704..(24704+512*64)
constexpr int SW_EA   = 9216;
constexpr int SW_ENC  = 16384;
constexpr int SW_DEC  = 24704;
constexpr int SMEM_FLOATS = SW_DEC + 512 * 64;   // 57472
constexpr int SMEM_BYTES  = SMEM_FLOATS * (int)sizeof(float);  // 229888
}

// ------------------------- global scratch ----------------------------------
__device__ float g_xT[L_ * F_ * B_];            // [t][f][b]
__device__ float g_seqT[(size_t)L_ * H_ * B_];  // [t][u][b] EA outputs (= h_t)
__device__ float g_hENC[2 * HB];                // ping-pong [u][b]
__device__ float g_hA[2 * HB];
__device__ float g_hB[2 * HB];
__device__ float g_din[B_];
__device__ unsigned g_arrive[NCTA * 32];        // one flag per 128B line
__device__ unsigned g_release;

// ------------------------- grid barrier (flag array) ------------------------
// Arrivals are parallel stores to distinct lines; CTA 0 aggregates (1 thread
// per peer flag) and publishes g_release. Generation values are monotonic
// across graph replays (base re-read from g_release at kernel start).
__device__ __forceinline__ void grid_sync(unsigned target) {
    __threadfence();
    __syncthreads();
    if (blockIdx.x == 0) {
        int t = threadIdx.x;
        if (t > 0 && t < NCTA) {
            while ((int)(*(volatile unsigned*)&g_arrive[t * 32] - target) < 0) { }
        }
        __syncthreads();
        if (t == 0) *(volatile unsigned*)&g_release = target;
    } else {
        if (threadIdx.x == 0) {
            *(volatile unsigned*)&g_arrive[blockIdx.x * 32] = target;
            while ((int)(*(volatile unsigned*)&g_release - target) < 0) { }
        }
        __syncthreads();
    }
    __threadfence();
    __syncthreads();
}

// ------------------------- math helpers ------------------------------------
__device__ __forceinline__ float sigf(float v) {
    return __fdividef(1.f, 1.f + __expf(-v));
}
__device__ __forceinline__ float tanh_(float v) {
    float t = __expf(2.f * v);
    return __fdividef(t - 1.f, t + 1.f);
}

// ------------------------- cp.async staging --------------------------------
#define CP_COMMIT() asm volatile("cp.async.commit_group;\n" ::: "memory")
#define CP_WAIT(N)  asm volatile("cp.async.wait_group %0;\n" :: "n"(N) : "memory")

// smem[r*64 + b] <- gmem[r*B + b0 + b], 16B chunks, L1-bypassing (.cg).
__device__ __forceinline__ void stage_cp(float* dst, const float* src,
                                         int nrows, int b0) {
    unsigned dbase = (unsigned)__cvta_generic_to_shared(dst);
    for (int i = threadIdx.x; i < nrows * 16; i += NTHR) {
        int r = i >> 4, b = (i & 15) << 2;
        asm volatile("cp.async.cg.shared.global [%0], [%1], 16;\n"
                     :: "r"(dbase + (unsigned)((r * 64 + b) * 4)),
                        "l"(src + (size_t)r * B_ + b0 + b) : "memory");
    }
}

// ------------------------- inner GEMV --------------------------------------
// a[8] = 4 gates x 2 batches. w0 = this unit's gate-0 row segment
// (float4-aligned), gate rows gstride floats apart. xs = [k][64] staging
// segment, tl = 2*lane. K % 4 == 0.
__device__ __forceinline__ void accum8v(float* a, const float* __restrict__ w0,
                                        int gstride, const float* __restrict__ xs,
                                        int K, int tl) {
    const float4* g0 = reinterpret_cast<const float4*>(w0);
    const float4* g1 = reinterpret_cast<const float4*>(w0 + gstride);
    const float4* g2 = reinterpret_cast<const float4*>(w0 + 2 * gstride);
    const float4* g3 = reinterpret_cast<const float4*>(w0 + 3 * gstride);
    const int K4 = K >> 2;
#pragma unroll 2
    for (int k4 = 0; k4 < K4; ++k4) {
        float4 w0v = g0[k4], w1v = g1[k4], w2v = g2[k4], w3v = g3[k4];
        const float* xb = xs + k4 * 256 + tl;
        float2 x0 = *reinterpret_cast<const float2*>(xb);
        float2 x1 = *reinterpret_cast<const float2*>(xb + 64);
        float2 x2 = *reinterpret_cast<const float2*>(xb + 128);
        float2 x3 = *reinterpret_cast<const float2*>(xb + 192);
        a[0] += w0v.x * x0.x; a[1] += w0v.x * x0.y;
        a[2] += w1v.x * x0.x; a[3] += w1v.x * x0.y;
        a[4] += w2v.x * x0.x; a[5] += w2v.x * x0.y;
        a[6] += w3v.x * x0.x; a[7] += w3v.x * x0.y;
        a[0] += w0v.y * x1.x; a[1] += w0v.y * x1.y;
        a[2] += w1v.y * x1.x; a[3] += w1v.y * x1.y;
        a[4] += w2v.y * x1.x; a[5] += w2v.y * x1.y;
        a[6] += w3v.y * x1.x; a[7] += w3v.y * x1.y;
        a[0] += w0v.z * x2.x; a[1] += w0v.z * x2.y;
        a[2] += w1v.z * x2.x; a[3] += w1v.z * x2.y;
        a[4] += w2v.z * x2.x; a[5] += w2v.z * x2.y;
        a[6] += w3v.z * x2.x; a[7] += w3v.z * x2.y;
        a[0] += w0v.w * x3.x; a[1] += w0v.w * x3.y;
        a[2] += w1v.w * x3.x; a[3] += w1v.w * x3.y;
        a[4] += w2v.w * x3.x; a[5] += w2v.w * x3.y;
        a[6] += w3v.w * x3.x; a[7] += w3v.w * x3.y;
    }
}

// ---------------------------------------------------------------------------
__global__ void __launch_bounds__(NTHR, 1)
ea_seq2seq_kernel(const float* __restrict__ x,    const float* __restrict__ s,
                  const float* __restrict__ Wf,   const float* __restrict__ bf,
                  const float* __restrict__ Wo,   const float* __restrict__ bo,
                  const float* __restrict__ Wi,   const float* __restrict__ bi,
                  const float* __restrict__ Wg,   const float* __restrict__ bg,
                  const float* __restrict__ Wsi,  const float* __restrict__ bsi,
                  const float* __restrict__ Wsg,  const float* __restrict__ bsg,
                  const float* __restrict__ eWih, const float* __restrict__ eWhh,
                  const float* __restrict__ ebih, const float* __restrict__ ebhh,
                  const float* __restrict__ dWih0, const float* __restrict__ dWhh0,
                  const float* __restrict__ dbih0, const float* __restrict__ dbhh0,
                  const float* __restrict__ dWih1, const float* __restrict__ dWhh1,
                  const float* __restrict__ dbih1, const float* __restrict__ dbhh1,
                  const float* __restrict__ fcW,  const float* __restrict__ fcb,
                  float* __restrict__ out)
{
    extern __shared__ float smem[];
    __shared__ unsigned s_base;

    const int tid  = threadIdx.x;
    const int bt   = blockIdx.x & 3;
    const int ut   = blockIdx.x >> 2;
    const int b0   = bt * 64;
    const int u0   = ut * 8;
    const int ul   = tid >> 5;
    const int lane = tid & 31;
    const int tl   = lane * 2;
    const int ug   = u0 + ul;
    const int gb   = b0 + tl;

    if (tid == 0) s_base = *(volatile unsigned*)&g_release;
    __syncthreads();
    unsigned bar = s_base;

    // ---------------- phase 0: transpose x (float4 over f), zero din -------
    {
        int gt = blockIdx.x * NTHR + tid;
        for (int i = gt; i < L_ * 8 * B_; i += NCTA * NTHR) {
            int t = i / (8 * B_);
            int r = i - t * (8 * B_);
            int f4 = r >> 8;
            int b  = r & 255;
            float4 v = *reinterpret_cast<const float4*>(
                x + (size_t)b * (L_ * F_) + t * F_ + f4 * 4);
            float* dst = g_xT + t * F_ * B_ + (f4 * 4) * B_ + b;
            dst[0]      = v.x;
            dst[B_]     = v.y;
            dst[2 * B_] = v.z;
            dst[3 * B_] = v.w;
        }
        if (blockIdx.x == 0) g_din[tid] = 0.f;
    }

    // static contributions si/sg (+ biases)
    float si0, si1, sg0, sg1;
    {
        si0 = si1 = bsi[ug];
        sg0 = sg1 = bsg[ug];
#pragma unroll
        for (int j = 0; j < S_; ++j) {
            float wiv = Wsi[ug * S_ + j];
            float wgv = Wsg[ug * S_ + j];
            float sv0 = s[gb * S_ + j];
            float sv1 = s[(gb + 1) * S_ + j];
            si0 += wiv * sv0; si1 += wiv * sv1;
            sg0 += wgv * sv0; sg1 += wgv * sv1;
        }
    }

    // EA weights -> smem, gate order f,o,i,g ; row length 288
    {
        float* sW = smem;
        const float* Ws[4] = {Wf, Wo, Wi, Wg};
        for (int i = tid; i < 4 * 8 * 288; i += NTHR) {
            int g = i / (8 * 288);
            int r = i - g * (8 * 288);
            int u = r / 288;
            int k = r - u * 288;
            sW[i] = Ws[g][(u0 + u) * 288 + k];
        }
    }
    const float bF = bf[ug], bO = bo[ug], bI = bi[ug], bG = bg[ug];

    grid_sync(++bar);   // x transpose + din visible everywhere

    // ---------------- phase 1: EA-LSTM over L steps ------------------------
    float c0 = 0.f, c1 = 0.f;
    {
        float* sW = smem;
        float* sX = smem + SW_EA;
        // prologue: stage x_0, zero h rows
        stage_cp(sX, g_xT, F_, b0);
        CP_COMMIT();
        for (int i = tid; i < H_ * 64; i += NTHR) sX[F_ * 64 + i] = 0.f;
        CP_WAIT(0);
        __syncthreads();

        for (int t = 0; t < L_; ++t) {
            float a[8] = {bF, bF, bO, bO, bI + si0, bI + si1, bG + sg0, bG + sg1};
            // x-side (K=32) — overlaps in-flight h staging groups
            accum8v(a, sW + ul * 288, 8 * 288, sX, 32, tl);
            CP_WAIT(1);              // h rows 0..127 landed (no-op at t=0)
            __syncthreads();
            accum8v(a, sW + ul * 288 + 32, 8 * 288, sX + 32 * 64, 128, tl);
            CP_WAIT(0);              // h rows 128..255 landed
            __syncthreads();
            accum8v(a, sW + ul * 288 + 160, 8 * 288, sX + 160 * 64, 128, tl);

            float f0 = sigf(a[0]), f1 = sigf(a[1]);
            float o0 = sigf(a[2]), o1 = sigf(a[3]);
            float i0 = sigf(a[4]), i1 = sigf(a[5]);
            float q0 = tanh_(a[6]), q1 = tanh_(a[7]);
            c0 = f0 * c0 + i0 * q0;
            c1 = f1 * c1 + i1 * q1;
            float2 hv = make_float2(o0 * tanh_(c0), o1 * tanh_(c1));

            *reinterpret_cast<float2*>(g_seqT + (size_t)t * HB + ug * B_ + gb) = hv;
            if (t == L_ - 1)
                *reinterpret_cast<float2*>(g_hENC + ug * B_ + gb) = hv;

            if (t + 1 < L_) {        // prefetch x_{t+1}: overlaps the barrier
                stage_cp(sX, g_xT + (t + 1) * F_ * B_, F_, b0);
                CP_COMMIT();
            }
            grid_sync(++bar);        // publish h_t (= seqT[t])
            if (t + 1 < L_) {        // stage h_t in two groups
                stage_cp(sX + 32 * 64,  g_seqT + (size_t)t * HB,            128, b0);
                CP_COMMIT();
                stage_cp(sX + 160 * 64, g_seqT + (size_t)t * HB + 128 * B_, 128, b0);
                CP_COMMIT();
                CP_WAIT(2);          // x_{t+1} ready (h groups still in flight)
                __syncthreads();
            }
        }
    }

    // ---------------- phase 2: encoder LSTM (gate order i,f,g,o) -----------
    {
        float* sW = smem;
        float* sX = smem + SW_ENC;
        for (int i = tid; i < 4 * 8 * 512; i += NTHR) {
            int g = i / (8 * 512);
            int r = i - g * (8 * 512);
            int u = r >> 9;
            int k = r & 511;
            int go = g * H_ + u0 + u;
            sW[i] = (k < 256) ? eWih[go * H_ + k] : eWhh[go * H_ + (k - 256)];
        }
        const float ebI = ebih[0 * H_ + ug] + ebhh[0 * H_ + ug];
        const float ebF = ebih[1 * H_ + ug] + ebhh[1 * H_ + ug];
        const float ebG = ebih[2 * H_ + ug] + ebhh[2 * H_ + ug];
        const float ebO = ebih[3 * H_ + ug] + ebhh[3 * H_ + ug];
        // prologue: stage seq[0] (x side) and h0 = hENC[0] in two groups
        stage_cp(sX, g_seqT, H_, b0);
        CP_COMMIT();
        stage_cp(sX + 256 * 64, g_hENC, 128, b0);
        CP_COMMIT();
        stage_cp(sX + 384 * 64, g_hENC + 128 * B_, 128, b0);
        CP_COMMIT();
        CP_WAIT(2);                  // x side ready
        __syncthreads();

        int p = 0;   // encoder c inherits EA final c (registers)
        for (int t = 0; t < L_; ++t) {
            float a[8] = {ebI, ebI, ebF, ebF, ebG, ebG, ebO, ebO};
            // x-side (K=256) — hides the two h staging groups
            accum8v(a, sW + ul * 512, 8 * 512, sX, 256, tl);
            CP_WAIT(1);
            __syncthreads();
            accum8v(a, sW + ul * 512 + 256, 8 * 512, sX + 256 * 64, 128, tl);
            CP_WAIT(0);
            __syncthreads();
            accum8v(a, sW + ul * 512 + 384, 8 * 512, sX + 384 * 64, 128, tl);

            float ii0 = sigf(a[0]), ii1 = sigf(a[1]);
            float ff0 = sigf(a[2]), ff1 = sigf(a[3]);
            float qg0 = tanh_(a[4]), qg1 = tanh_(a[5]);
            float oo0 = sigf(a[6]), oo1 = sigf(a[7]);
            c0 = ff0 * c0 + ii0 * qg0;
            c1 = ff1 * c1 + ii1 * qg1;
            float2 hv = make_float2(oo0 * tanh_(c0), oo1 * tanh_(c1));

            *reinterpret_cast<float2*>(g_hENC + (1 - p) * HB + ug * B_ + gb) = hv;
            if (t == L_ - 1) {
                *reinterpret_cast<float2*>(g_hA + ug * B_ + gb) = hv;
                *reinterpret_cast<float2*>(g_hB + ug * B_ + gb) = hv;
            }

            if (t + 1 < L_) {        // prefetch seq[t+1]: overlaps the barrier
                stage_cp(sX, g_seqT + (size_t)(t + 1) * HB, H_, b0);
                CP_COMMIT();
            }
            grid_sync(++bar);        // publish h_t
            if (t + 1 < L_) {
                const float* hsrc = g_hENC + (1 - p) * HB;
                stage_cp(sX + 256 * 64, hsrc,            128, b0);
                CP_COMMIT();
                stage_cp(sX + 384 * 64, hsrc + 128 * B_, 128, b0);
                CP_COMMIT();
                CP_WAIT(2);
                __syncthreads();
            }
            p ^= 1;
        }
    }

    // ---------------- phase 3: decoder (2 layers, 24 steps) ----------------
    {
        float* sW0 = smem;                 // 32 rows x 260: [Whh0 | Wih0 | 0,0,0]
        float* sW1 = smem + 8320;          // 32 rows x 512: [Wih1 | Whh1]
        float* sX  = smem + SW_DEC;
        for (int i = tid; i < 32 * 260; i += NTHR) {
            int row = i / 260;
            int k   = i - row * 260;
            int g = row >> 3, u = row & 7;
            int go = g * H_ + u0 + u;
            float v = 0.f;
            if (k < 256)       v = dWhh0[go * H_ + k];
            else if (k == 256) v = dWih0[go];
            sW0[i] = v;
        }
        for (int i = tid; i < 32 * 512; i += NTHR) {
            int row = i >> 9;
            int k   = i & 511;
            int g = row >> 3, u = row & 7;
            int go = g * H_ + u0 + u;
            sW1[i] = (k < 256) ? dWih1[go * H_ + k] : dWhh1[go * H_ + (k - 256)];
        }
        // zero pad rows 257..259 once
        for (int i = tid; i < 3 * 64; i += NTHR) sX[257 * 64 + i] = 0.f;
        const float d0I = dbih0[0*H_+ug] + dbhh0[0*H_+ug];
        const float d0F = dbih0[1*H_+ug] + dbhh0[1*H_+ug];
        const float d0G = dbih0[2*H_+ug] + dbhh0[2*H_+ug];
        const float d0O = dbih0[3*H_+ug] + dbhh0[3*H_+ug];
        const float d1I = dbih1[0*H_+ug] + dbhh1[0*H_+ug];
        const float d1F = dbih1[1*H_+ug] + dbhh1[1*H_+ug];
        const float d1G = dbih1[2*H_+ug] + dbhh1[2*H_+ug];
        const float d1O = dbih1[3*H_+ug] + dbhh1[3*H_+ug];
        const float fcb0 = fcb[0];
        float cA0 = c0, cA1 = c1, cB0 = c0, cB1 = c1;
        __syncthreads();

        int p = 0;
        for (int st = 0; st < HOR_; ++st) {
            // ---- layer 0: x = [hA(256) | din(1) | pad(3)], K=260 ----
            stage_cp(sX, g_hA + p * HB, H_, b0);
            if (tid < 16) {
                unsigned da = (unsigned)__cvta_generic_to_shared(sX + 256 * 64 + tid * 4);
                asm volatile("cp.async.cg.shared.global [%0], [%1], 16;\n"
                             :: "r"(da), "l"(g_din + b0 + tid * 4) : "memory");
            }
            CP_COMMIT();
            CP_WAIT(0);
            __syncthreads();
            {
                float a[8] = {d0I, d0I, d0F, d0F, d0G, d0G, d0O, d0O};
                accum8v(a, sW0 + ul * 260, 8 * 260, sX, 260, tl);
                float ii0 = sigf(a[0]), ii1 = sigf(a[1]);
                float ff0 = sigf(a[2]), ff1 = sigf(a[3]);
                float qg0 = tanh_(a[4]), qg1 = tanh_(a[5]);
                float oo0 = sigf(a[6]), oo1 = sigf(a[7]);
                cA0 = ff0 * cA0 + ii0 * qg0;
                cA1 = ff1 * cA1 + ii1 * qg1;
                float2 hv = make_float2(oo0 * tanh_(cA0), oo1 * tanh_(cA1));
                *reinterpret_cast<float2*>(g_hA + (1 - p) * HB + ug * B_ + gb) = hv;
            }
            grid_sync(++bar);

            // ---- layer 1: x = [hA_new(256) | hB(256)], K=512 ----
            stage_cp(sX, g_hA + (1 - p) * HB, H_, b0);
            stage_cp(sX + 256 * 64, g_hB + p * HB, H_, b0);
            CP_COMMIT();
            CP_WAIT(0);
            __syncthreads();
            {
                float a[8] = {d1I, d1I, d1F, d1F, d1G, d1G, d1O, d1O};
                accum8v(a, sW1 + ul * 512, 8 * 512, sX, 512, tl);
                float ii0 = sigf(a[0]), ii1 = sigf(a[1]);
                float ff0 = sigf(a[2]), ff1 = sigf(a[3]);
                float qg0 = tanh_(a[4]), qg1 = tanh_(a[5]);
                float oo0 = sigf(a[6]), oo1 = sigf(a[7]);
                cB0 = ff0 * cB0 + ii0 * qg0;
                cB1 = ff1 * cB1 + ii1 * qg1;
                float2 hv = make_float2(oo0 * tanh_(cB0), oo1 * tanh_(cB1));
                *reinterpret_cast<float2*>(g_hB + (1 - p) * HB + ug * B_ + gb) = hv;
            }
            grid_sync(++bar);

            // ---- output head: pred = hB @ fcW + fcb ----
            if (ut == 0) {
                int bloc = tid >> 2, q = tid & 3;
                int gb2 = b0 + bloc;
                const float* hb = g_hB + (1 - p) * HB;
                float v = 0.f;
#pragma unroll 4
                for (int k = q * 64; k < q * 64 + 64; ++k)
                    v += __ldcg(&hb[k * B_ + gb2]) * fcW[k];
                v += __shfl_xor_sync(0xffffffffu, v, 1);
                v += __shfl_xor_sync(0xffffffffu, v, 2);
                if (q == 0) {
                    float pr = v + fcb0;
                    out[gb2 * HOR_ + st] = pr;
                    g_din[gb2] = pr;
                }
            }
            grid_sync(++bar);
            p ^= 1;
        }
    }
}

// ---------------------------------------------------------------------------
extern "C" void kernel_launch(void* const* d_in, const int* in_sizes, int n_in,
                              void* d_out, int out_size) {
    (void)in_sizes; (void)n_in; (void)out_size;
    const float* x     = (const float*)d_in[0];
    const float* s     = (const float*)d_in[1];
    const float* Wf    = (const float*)d_in[2];
    const float* bf    = (const float*)d_in[3];
    const float* Wo    = (const float*)d_in[4];
    const float* bo    = (const float*)d_in[5];
    const float* Wi    = (const float*)d_in[6];
    const float* bi    = (const float*)d_in[7];
    const float* Wg    = (const float*)d_in[8];
    const float* bg    = (const float*)d_in[9];
    const float* Wsi   = (const float*)d_in[10];
    const float* bsi   = (const float*)d_in[11];
    const float* Wsg   = (const float*)d_in[12];
    const float* bsg   = (const float*)d_in[13];
    const float* eWih  = (const float*)d_in[14];
    const float* eWhh  = (const float*)d_in[15];
    const float* ebih  = (const float*)d_in[16];
    const float* ebhh  = (const float*)d_in[17];
    const float* dWih0 = (const float*)d_in[18];
    const float* dWhh0 = (const float*)d_in[19];
    const float* dbih0 = (const float*)d_in[20];
    const float* dbhh0 = (const float*)d_in[21];
    const float* dWih1 = (const float*)d_in[22];
    const float* dWhh1 = (const float*)d_in[23];
    const float* dbih1 = (const float*)d_in[24];
    const float* dbhh1 = (const float*)d_in[25];
    const float* fcW   = (const float*)d_in[26];
    const float* fcb   = (const float*)d_in[27];

    cudaFuncSetAttribute(ea_seq2seq_kernel,
                         cudaFuncAttributeMaxDynamicSharedMemorySize, SMEM_BYTES);
    ea_seq2seq_kernel<<<NCTA, NTHR, SMEM_BYTES>>>(
        x, s, Wf, bf, Wo, bo, Wi, bi, Wg, bg, Wsi, bsi, Wsg, bsg,
        eWih, eWhh, ebih, ebhh,
        dWih0, dWhh0, dbih0, dbhh0, dWih1, dWhh1, dbih1, dbhh1,
        fcW, fcb, (float*)d_out);
}

// round 15
// speedup vs baseline: 1.2511x; 1.1205x over previous
#include <cuda_runtime.h>

// ---------------------------------------------------------------------------
// EASeq2SeqLSTM persistent-kernel fp32, v4.1 (v4 resubmit, cleaned).
// B=256, L=365, F=32, S=27, H=256, HOR=24, NT=1.
// 128 CTAs x 256 threads, 1 CTA/SM.
// v4: bt-scoped symmetric 32-CTA barriers (st.release/ld.acquire flags,
//     no threadfence -> no CCTL.IVALL, no central aggregation hop),
//     bt-local phase-0 transpose (no full-grid barrier anywhere).
// ---------------------------------------------------------------------------

namespace {
constexpr int B_   = 256;
constexpr int L_   = 365;
constexpr int F_   = 32;
constexpr int S_   = 27;
constexpr int H_   = 256;
constexpr int HOR_ = 24;
constexpr int HB   = H_ * B_;      // 65536
constexpr int NCTA = 128;
constexpr int NTHR = 256;
constexpr int GSZ  = 32;           // CTAs per bt group

constexpr int SW_EA   = 9216;
constexpr int SW_ENC  = 16384;
constexpr int SW_DEC  = 24704;
constexpr int SMEM_FLOATS = SW_DEC + 512 * 64;   // 57472
constexpr int SMEM_BYTES  = SMEM_FLOATS * (int)sizeof(float);  // 229888
}

// ------------------------- global scratch ----------------------------------
__device__ float g_xT[L_ * F_ * B_];            // [t][f][b]
__device__ float g_seqT[(size_t)L_ * H_ * B_];  // [t][u][b] EA outputs (= h_t)
__device__ float g_hENC[2 * HB];                // ping-pong [u][b]
__device__ float g_hA[2 * HB];
__device__ float g_hB[2 * HB];
__device__ float g_din[B_];
__device__ unsigned g_flag[4 * GSZ * 32];       // [bt][rank], 128B apart

// ------------------------- acquire/release helpers -------------------------
__device__ __forceinline__ unsigned ld_acq(const unsigned* p) {
    unsigned v;
    asm volatile("ld.acquire.gpu.u32 %0, [%1];" : "=r"(v) : "l"(p) : "memory");
    return v;
}
__device__ __forceinline__ void st_rel(unsigned* p, unsigned v) {
    asm volatile("st.release.gpu.u32 [%0], %1;" :: "l"(p), "r"(v) : "memory");
}

// ------------------------- bt-group barrier --------------------------------
// Symmetric: each CTA releases its own flag; 32 threads of every CTA poll all
// 32 group flags. No central hop, no MEMBAR. Flags are monotonic across
// graph replays (base re-read at kernel start). Fast CTAs over-running is
// safe: flag >= target satisfies the signed-difference wait.
__device__ __forceinline__ void group_sync(unsigned* flags, int rank,
                                           unsigned target) {
    __syncthreads();                       // CTA's writes of this step done
    if (threadIdx.x == 0)
        st_rel(flags + rank * 32, target); // release: prior STG visible
    if (threadIdx.x < GSZ) {
        const unsigned* f = flags + threadIdx.x * 32;
        while ((int)(ld_acq(f) - target) < 0) { }
    }
    __syncthreads();                       // broadcast acquire CTA-wide
}

// ------------------------- math helpers ------------------------------------
__device__ __forceinline__ float sigf(float v) {
    return __fdividef(1.f, 1.f + __expf(-v));
}
__device__ __forceinline__ float tanh_(float v) {
    float t = __expf(2.f * v);
    return __fdividef(t - 1.f, t + 1.f);
}

// ------------------------- cp.async staging --------------------------------
#define CP_COMMIT() asm volatile("cp.async.commit_group;\n" ::: "memory")
#define CP_WAIT(N)  asm volatile("cp.async.wait_group %0;\n" :: "n"(N) : "memory")

// smem[r*64 + b] <- gmem[r*B + b0 + b], 16B chunks, L1-bypassing (.cg).
__device__ __forceinline__ void stage_cp(float* dst, const float* src,
                                         int nrows, int b0) {
    unsigned dbase = (unsigned)__cvta_generic_to_shared(dst);
    for (int i = threadIdx.x; i < nrows * 16; i += NTHR) {
        int r = i >> 4, b = (i & 15) << 2;
        asm volatile("cp.async.cg.shared.global [%0], [%1], 16;\n"
                     :: "r"(dbase + (unsigned)((r * 64 + b) * 4)),
                        "l"(src + (size_t)r * B_ + b0 + b) : "memory");
    }
}

// ------------------------- inner GEMV --------------------------------------
// a[8] = 4 gates x 2 batches. w0 = this unit's gate-0 row segment
// (float4-aligned), gate rows gstride floats apart. xs = [k][64] staging
// segment, tl = 2*lane. K % 4 == 0.
__device__ __forceinline__ void accum8v(float* a, const float* __restrict__ w0,
                                        int gstride, const float* __restrict__ xs,
                                        int K, int tl) {
    const float4* g0 = reinterpret_cast<const float4*>(w0);
    const float4* g1 = reinterpret_cast<const float4*>(w0 + gstride);
    const float4* g2 = reinterpret_cast<const float4*>(w0 + 2 * gstride);
    const float4* g3 = reinterpret_cast<const float4*>(w0 + 3 * gstride);
    const int K4 = K >> 2;
#pragma unroll 2
    for (int k4 = 0; k4 < K4; ++k4) {
        float4 w0v = g0[k4], w1v = g1[k4], w2v = g2[k4], w3v = g3[k4];
        const float* xb = xs + k4 * 256 + tl;
        float2 x0 = *reinterpret_cast<const float2*>(xb);
        float2 x1 = *reinterpret_cast<const float2*>(xb + 64);
        float2 x2 = *reinterpret_cast<const float2*>(xb + 128);
        float2 x3 = *reinterpret_cast<const float2*>(xb + 192);
        a[0] += w0v.x * x0.x; a[1] += w0v.x * x0.y;
        a[2] += w1v.x * x0.x; a[3] += w1v.x * x0.y;
        a[4] += w2v.x * x0.x; a[5] += w2v.x * x0.y;
        a[6] += w3v.x * x0.x; a[7] += w3v.x * x0.y;
        a[0] += w0v.y * x1.x; a[1] += w0v.y * x1.y;
        a[2] += w1v.y * x1.x; a[3] += w1v.y * x1.y;
        a[4] += w2v.y * x1.x; a[5] += w2v.y * x1.y;
        a[6] += w3v.y * x1.x; a[7] += w3v.y * x1.y;
        a[0] += w0v.z * x2.x; a[1] += w0v.z * x2.y;
        a[2] += w1v.z * x2.x; a[3] += w1v.z * x2.y;
        a[4] += w2v.z * x2.x; a[5] += w2v.z * x2.y;
        a[6] += w3v.z * x2.x; a[7] += w3v.z * x2.y;
        a[0] += w0v.w * x3.x; a[1] += w0v.w * x3.y;
        a[2] += w1v.w * x3.x; a[3] += w1v.w * x3.y;
        a[4] += w2v.w * x3.x; a[5] += w2v.w * x3.y;
        a[6] += w3v.w * x3.x; a[7] += w3v.w * x3.y;
    }
}

// ---------------------------------------------------------------------------
__global__ void __launch_bounds__(NTHR, 1)
ea_seq2seq_kernel(const float* __restrict__ x,    const float* __restrict__ s,
                  const float* __restrict__ Wf,   const float* __restrict__ bf,
                  const float* __restrict__ Wo,   const float* __restrict__ bo,
                  const float* __restrict__ Wi,   const float* __restrict__ bi,
                  const float* __restrict__ Wg,   const float* __restrict__ bg,
                  const float* __restrict__ Wsi,  const float* __restrict__ bsi,
                  const float* __restrict__ Wsg,  const float* __restrict__ bsg,
                  const float* __restrict__ eWih, const float* __restrict__ eWhh,
                  const float* __restrict__ ebih, const float* __restrict__ ebhh,
                  const float* __restrict__ dWih0, const float* __restrict__ dWhh0,
                  const float* __restrict__ dbih0, const float* __restrict__ dbhh0,
                  const float* __restrict__ dWih1, const float* __restrict__ dWhh1,
                  const float* __restrict__ dbih1, const float* __restrict__ dbhh1,
                  const float* __restrict__ fcW,  const float* __restrict__ fcb,
                  float* __restrict__ out)
{
    extern __shared__ float smem[];
    __shared__ unsigned s_base;

    const int tid  = threadIdx.x;
    const int bt   = blockIdx.x & 3;
    const int ut   = blockIdx.x >> 2;   // rank within bt group
    const int b0   = bt * 64;
    const int u0   = ut * 8;
    const int ul   = tid >> 5;
    const int lane = tid & 31;
    const int tl   = lane * 2;
    const int ug   = u0 + ul;
    const int gb   = b0 + tl;

    unsigned* flags = g_flag + bt * (GSZ * 32);

    if (tid == 0) s_base = *(volatile unsigned*)(flags);  // group leader flag
    __syncthreads();
    unsigned bar = s_base;

    // ---------------- phase 0: transpose x for this bt group only ----------
    {
        int gidx = ut * NTHR + tid;   // index within the 32-CTA group
        for (int i = gidx; i < L_ * 8 * 64; i += GSZ * NTHR) {
            int t = i / (8 * 64);
            int r = i - t * (8 * 64);
            int f4 = r >> 6;
            int b  = (r & 63) + b0;
            float4 v = *reinterpret_cast<const float4*>(
                x + (size_t)b * (L_ * F_) + t * F_ + f4 * 4);
            float* dst = g_xT + t * F_ * B_ + (f4 * 4) * B_ + b;
            dst[0]      = v.x;
            dst[B_]     = v.y;
            dst[2 * B_] = v.z;
            dst[3 * B_] = v.w;
        }
        if (ut == 0 && tid < 64) g_din[b0 + tid] = 0.f;
    }

    // static contributions si/sg (+ biases)
    float si0, si1, sg0, sg1;
    {
        si0 = si1 = bsi[ug];
        sg0 = sg1 = bsg[ug];
#pragma unroll
        for (int j = 0; j < S_; ++j) {
            float wiv = Wsi[ug * S_ + j];
            float wgv = Wsg[ug * S_ + j];
            float sv0 = s[gb * S_ + j];
            float sv1 = s[(gb + 1) * S_ + j];
            si0 += wiv * sv0; si1 += wiv * sv1;
            sg0 += wgv * sv0; sg1 += wgv * sv1;
        }
    }

    // EA weights -> smem, gate order f,o,i,g ; row length 288
    {
        float* sW = smem;
        const float* Ws[4] = {Wf, Wo, Wi, Wg};
        for (int i = tid; i < 4 * 8 * 288; i += NTHR) {
            int g = i / (8 * 288);
            int r = i - g * (8 * 288);
            int u = r / 288;
            int k = r - u * 288;
            sW[i] = Ws[g][(u0 + u) * 288 + k];
        }
    }
    const float bF = bf[ug], bO = bo[ug], bI = bi[ug], bG = bg[ug];

    group_sync(flags, ut, ++bar);   // x transpose + din visible in group

    // ---------------- phase 1: EA-LSTM over L steps ------------------------
    float c0 = 0.f, c1 = 0.f;
    {
        float* sW = smem;
        float* sX = smem + SW_EA;
        stage_cp(sX, g_xT, F_, b0);
        CP_COMMIT();
        for (int i = tid; i < H_ * 64; i += NTHR) sX[F_ * 64 + i] = 0.f;
        CP_WAIT(0);
        __syncthreads();

        for (int t = 0; t < L_; ++t) {
            float a[8] = {bF, bF, bO, bO, bI + si0, bI + si1, bG + sg0, bG + sg1};
            accum8v(a, sW + ul * 288, 8 * 288, sX, 32, tl);
            CP_WAIT(1);
            __syncthreads();
            accum8v(a, sW + ul * 288 + 32, 8 * 288, sX + 32 * 64, 128, tl);
            CP_WAIT(0);
            __syncthreads();
            accum8v(a, sW + ul * 288 + 160, 8 * 288, sX + 160 * 64, 128, tl);

            float f0 = sigf(a[0]), f1 = sigf(a[1]);
            float o0 = sigf(a[2]), o1 = sigf(a[3]);
            float i0 = sigf(a[4]), i1 = sigf(a[5]);
            float q0 = tanh_(a[6]), q1 = tanh_(a[7]);
            c0 = f0 * c0 + i0 * q0;
            c1 = f1 * c1 + i1 * q1;
            float2 hv = make_float2(o0 * tanh_(c0), o1 * tanh_(c1));

            *reinterpret_cast<float2*>(g_seqT + (size_t)t * HB + ug * B_ + gb) = hv;
            if (t == L_ - 1)
                *reinterpret_cast<float2*>(g_hENC + ug * B_ + gb) = hv;

            if (t + 1 < L_) {
                stage_cp(sX, g_xT + (t + 1) * F_ * B_, F_, b0);
                CP_COMMIT();
            }
            group_sync(flags, ut, ++bar);          // publish h_t (= seqT[t])
            if (t + 1 < L_) {
                stage_cp(sX + 32 * 64,  g_seqT + (size_t)t * HB,            128, b0);
                CP_COMMIT();
                stage_cp(sX + 160 * 64, g_seqT + (size_t)t * HB + 128 * B_, 128, b0);
                CP_COMMIT();
                CP_WAIT(2);
                __syncthreads();
            }
        }
    }

    // ---------------- phase 2: encoder LSTM (gate order i,f,g,o) -----------
    {
        float* sW = smem;
        float* sX = smem + SW_ENC;
        for (int i = tid; i < 4 * 8 * 512; i += NTHR) {
            int g = i / (8 * 512);
            int r = i - g * (8 * 512);
            int u = r >> 9;
            int k = r & 511;
            int go = g * H_ + u0 + u;
            sW[i] = (k < 256) ? eWih[go * H_ + k] : eWhh[go * H_ + (k - 256)];
        }
        const float ebI = ebih[0 * H_ + ug] + ebhh[0 * H_ + ug];
        const float ebF = ebih[1 * H_ + ug] + ebhh[1 * H_ + ug];
        const float ebG = ebih[2 * H_ + ug] + ebhh[2 * H_ + ug];
        const float ebO = ebih[3 * H_ + ug] + ebhh[3 * H_ + ug];
        stage_cp(sX, g_seqT, H_, b0);
        CP_COMMIT();
        stage_cp(sX + 256 * 64, g_hENC, 128, b0);
        CP_COMMIT();
        stage_cp(sX + 384 * 64, g_hENC + 128 * B_, 128, b0);
        CP_COMMIT();
        CP_WAIT(2);
        __syncthreads();

        int p = 0;   // encoder c inherits EA final c (registers)
        for (int t = 0; t < L_; ++t) {
            float a[8] = {ebI, ebI, ebF, ebF, ebG, ebG, ebO, ebO};
            accum8v(a, sW + ul * 512, 8 * 512, sX, 256, tl);
            CP_WAIT(1);
            __syncthreads();
            accum8v(a, sW + ul * 512 + 256, 8 * 512, sX + 256 * 64, 128, tl);
            CP_WAIT(0);
            __syncthreads();
            accum8v(a, sW + ul * 512 + 384, 8 * 512, sX + 384 * 64, 128, tl);

            float ii0 = sigf(a[0]), ii1 = sigf(a[1]);
            float ff0 = sigf(a[2]), ff1 = sigf(a[3]);
            float qg0 = tanh_(a[4]), qg1 = tanh_(a[5]);
            float oo0 = sigf(a[6]), oo1 = sigf(a[7]);
            c0 = ff0 * c0 + ii0 * qg0;
            c1 = ff1 * c1 + ii1 * qg1;
            float2 hv = make_float2(oo0 * tanh_(c0), oo1 * tanh_(c1));

            *reinterpret_cast<float2*>(g_hENC + (1 - p) * HB + ug * B_ + gb) = hv;
            if (t == L_ - 1) {
                *reinterpret_cast<float2*>(g_hA + ug * B_ + gb) = hv;
                *reinterpret_cast<float2*>(g_hB + ug * B_ + gb) = hv;
            }

            if (t + 1 < L_) {
                stage_cp(sX, g_seqT + (size_t)(t + 1) * HB, H_, b0);
                CP_COMMIT();
            }
            group_sync(flags, ut, ++bar);          // publish h_t
            if (t + 1 < L_) {
                const float* hsrc = g_hENC + (1 - p) * HB;
                stage_cp(sX + 256 * 64, hsrc,            128, b0);
                CP_COMMIT();
                stage_cp(sX + 384 * 64, hsrc + 128 * B_, 128, b0);
                CP_COMMIT();
                CP_WAIT(2);
                __syncthreads();
            }
            p ^= 1;
        }
    }

    // ---------------- phase 3: decoder (2 layers, 24 steps) ----------------
    {
        float* sW0 = smem;                 // 32 rows x 260: [Whh0 | Wih0 | 0,0,0]
        float* sW1 = smem + 8320;          // 32 rows x 512: [Wih1 | Whh1]
        float* sX  = smem + SW_DEC;
        for (int i = tid; i < 32 * 260; i += NTHR) {
            int row = i / 260;
            int k   = i - row * 260;
            int g = row >> 3, u = row & 7;
            int go = g * H_ + u0 + u;
            float v = 0.f;
            if (k < 256)       v = dWhh0[go * H_ + k];
            else if (k == 256) v = dWih0[go];
            sW0[i] = v;
        }
        for (int i = tid; i < 32 * 512; i += NTHR) {
            int row = i >> 9;
            int k   = i & 511;
            int g = row >> 3, u = row & 7;
            int go = g * H_ + u0 + u;
            sW1[i] = (k < 256) ? dWih1[go * H_ + k] : dWhh1[go * H_ + (k - 256)];
        }
        for (int i = tid; i < 3 * 64; i += NTHR) sX[257 * 64 + i] = 0.f;
        const float d0I = dbih0[0*H_+ug] + dbhh0[0*H_+ug];
        const float d0F = dbih0[1*H_+ug] + dbhh0[1*H_+ug];
        const float d0G = dbih0[2*H_+ug] + dbhh0[2*H_+ug];
        const float d0O = dbih0[3*H_+ug] + dbhh0[3*H_+ug];
        const float d1I = dbih1[0*H_+ug] + dbhh1[0*H_+ug];
        const float d1F = dbih1[1*H_+ug] + dbhh1[1*H_+ug];
        const float d1G = dbih1[2*H_+ug] + dbhh1[2*H_+ug];
        const float d1O = dbih1[3*H_+ug] + dbhh1[3*H_+ug];
        const float fcb0 = fcb[0];
        float cA0 = c0, cA1 = c1, cB0 = c0, cB1 = c1;
        __syncthreads();

        int p = 0;
        for (int st = 0; st < HOR_; ++st) {
            // ---- layer 0: x = [hA(256) | din(1) | pad(3)], K=260 ----
            stage_cp(sX, g_hA + p * HB, H_, b0);
            if (tid < 16) {
                unsigned da = (unsigned)__cvta_generic_to_shared(sX + 256 * 64 + tid * 4);
                asm volatile("cp.async.cg.shared.global [%0], [%1], 16;\n"
                             :: "r"(da), "l"(g_din + b0 + tid * 4) : "memory");
            }
            CP_COMMIT();
            CP_WAIT(0);
            __syncthreads();
            {
                float a[8] = {d0I, d0I, d0F, d0F, d0G, d0G, d0O, d0O};
                accum8v(a, sW0 + ul * 260, 8 * 260, sX, 260, tl);
                float ii0 = sigf(a[0]), ii1 = sigf(a[1]);
                float ff0 = sigf(a[2]), ff1 = sigf(a[3]);
                float qg0 = tanh_(a[4]), qg1 = tanh_(a[5]);
                float oo0 = sigf(a[6]), oo1 = sigf(a[7]);
                cA0 = ff0 * cA0 + ii0 * qg0;
                cA1 = ff1 * cA1 + ii1 * qg1;
                float2 hv = make_float2(oo0 * tanh_(cA0), oo1 * tanh_(cA1));
                *reinterpret_cast<float2*>(g_hA + (1 - p) * HB + ug * B_ + gb) = hv;
            }
            group_sync(flags, ut, ++bar);

            // ---- layer 1: x = [hA_new(256) | hB(256)], K=512 ----
            stage_cp(sX, g_hA + (1 - p) * HB, H_, b0);
            stage_cp(sX + 256 * 64, g_hB + p * HB, H_, b0);
            CP_COMMIT();
            CP_WAIT(0);
            __syncthreads();
            {
                float a[8] = {d1I, d1I, d1F, d1F, d1G, d1G, d1O, d1O};
                accum8v(a, sW1 + ul * 512, 8 * 512, sX, 512, tl);
                float ii0 = sigf(a[0]), ii1 = sigf(a[1]);
                float ff0 = sigf(a[2]), ff1 = sigf(a[3]);
                float qg0 = tanh_(a[4]), qg1 = tanh_(a[5]);
                float oo0 = sigf(a[6]), oo1 = sigf(a[7]);
                cB0 = ff0 * cB0 + ii0 * qg0;
                cB1 = ff1 * cB1 + ii1 * qg1;
                float2 hv = make_float2(oo0 * tanh_(cB0), oo1 * tanh_(cB1));
                *reinterpret_cast<float2*>(g_hB + (1 - p) * HB + ug * B_ + gb) = hv;
            }
            group_sync(flags, ut, ++bar);

            // ---- output head: pred = hB @ fcW + fcb ----
            if (ut == 0) {
                int bloc = tid >> 2, q = tid & 3;
                int gb2 = b0 + bloc;
                const float* hb = g_hB + (1 - p) * HB;
                float v = 0.f;
#pragma unroll 4
                for (int k = q * 64; k < q * 64 + 64; ++k)
                    v += __ldcg(&hb[k * B_ + gb2]) * fcW[k];
                v += __shfl_xor_sync(0xffffffffu, v, 1);
                v += __shfl_xor_sync(0xffffffffu, v, 2);
                if (q == 0) {
                    float pr = v + fcb0;
                    out[gb2 * HOR_ + st] = pr;
                    g_din[gb2] = pr;
                }
            }
            group_sync(flags, ut, ++bar);
            p ^= 1;
        }
    }
}

// ---------------------------------------------------------------------------
extern "C" void kernel_launch(void* const* d_in, const int* in_sizes, int n_in,
                              void* d_out, int out_size) {
    (void)in_sizes; (void)n_in; (void)out_size;
    const float* x     = (const float*)d_in[0];
    const float* s     = (const float*)d_in[1];
    const float* Wf    = (const float*)d_in[2];
    const float* bf    = (const float*)d_in[3];
    const float* Wo    = (const float*)d_in[4];
    const float* bo    = (const float*)d_in[5];
    const float* Wi    = (const float*)d_in[6];
    const float* bi    = (const float*)d_in[7];
    const float* Wg    = (const float*)d_in[8];
    const float* bg    = (const float*)d_in[9];
    const float* Wsi   = (const float*)d_in[10];
    const float* bsi   = (const float*)d_in[11];
    const float* Wsg   = (const float*)d_in[12];
    const float* bsg   = (const float*)d_in[13];
    const float* eWih  = (const float*)d_in[14];
    const float* eWhh  = (const float*)d_in[15];
    const float* ebih  = (const float*)d_in[16];
    const float* ebhh  = (const float*)d_in[17];
    const float* dWih0 = (const float*)d_in[18];
    const float* dWhh0 = (const float*)d_in[19];
    const float* dbih0 = (const float*)d_in[20];
    const float* dbhh0 = (const float*)d_in[21];
    const float* dWih1 = (const float*)d_in[22];
    const float* dWhh1 = (const float*)d_in[23];
    const float* dbih1 = (const float*)d_in[24];
    const float* dbhh1 = (const float*)d_in[25];
    const float* fcW   = (const float*)d_in[26];
    const float* fcb   = (const float*)d_in[27];

    cudaFuncSetAttribute(ea_seq2seq_kernel,
                         cudaFuncAttributeMaxDynamicSharedMemorySize, SMEM_BYTES);
    ea_seq2seq_kernel<<<NCTA, NTHR, SMEM_BYTES>>>(
        x, s, Wf, bf, Wo, bo, Wi, bi, Wg, bg, Wsi, bsi, Wsg, bsg,
        eWih, eWhh, ebih, ebhh,
        dWih0, dWhh0, dbih0, dbhh0, dWih1, dWhh1, dbih1, dbhh1,
        fcW, fcb, (float*)d_out);
}